// round 17
// baseline (speedup 1.0000x reference)
#include <cuda_runtime.h>
#include <cuda_fp16.h>
#include <math.h>
#include <stdint.h>

#define TT 64
#define BB 64
#define SS 512
#define AA 16
#define RR 64
#define HH 32
#define KI 8192
#define EPSV 1e-6f

// ---------------- scratch (no allocations allowed) ----------------
__device__ float d_T[AA * SS * SS];            // transition [k][i][j] (16.8 MB)
__device__ float d_G[SS * SS];
__device__ float d_p[AA * SS];
__device__ float d_alpha_a[TT * BB * AA];
__device__ float d_taupdf[HH];
__device__ float d_partial[32 * BB * SS];      // split-K partials [ks][n][j] (4 MB)
__device__ float d_pi_part[8 * TT * BB * AA];
__device__ __align__(16) __half d_Tt[SS * KI];  // T^T fp16 (8 MB)
__device__ __align__(16) __half d_ab[BB * KI];  // Ã = a⊗bel, fp16 (1 MB)
__device__ unsigned int g_cnt;                  // grid barrier counter

// ---------------- generic helpers ----------------
__device__ __forceinline__ void fma2(unsigned long long& d, unsigned long long a,
                                     unsigned long long b) {
    asm("fma.rn.f32x2 %0, %1, %2, %0;" : "+l"(d) : "l"(a), "l"(b));
}
__device__ __forceinline__ unsigned long long pack2(float x) {
    unsigned long long r;
    unsigned int xi = __float_as_uint(x);
    asm("mov.b64 %0, {%1, %1};" : "=l"(r) : "r"(xi));
    return r;
}
// block reduce over nw warps (nw <= 16), buf must have >= nw floats
__device__ __forceinline__ float bmaxN(float v, float* buf, int nw) {
    int lane = threadIdx.x & 31, w = threadIdx.x >> 5;
#pragma unroll
    for (int o = 16; o; o >>= 1) v = fmaxf(v, __shfl_xor_sync(0xffffffffu, v, o));
    if (!lane) buf[w] = v;
    __syncthreads();
    if (w == 0) {
        float x = (lane < nw) ? buf[lane] : -3.402823466e38f;
#pragma unroll
        for (int o = 8; o; o >>= 1) x = fmaxf(x, __shfl_xor_sync(0xffffffffu, x, o));
        if (!lane) buf[0] = x;
    }
    __syncthreads();
    float r = buf[0];
    __syncthreads();
    return r;
}
__device__ __forceinline__ float bsumN(float v, float* buf, int nw) {
    int lane = threadIdx.x & 31, w = threadIdx.x >> 5;
#pragma unroll
    for (int o = 16; o; o >>= 1) v += __shfl_xor_sync(0xffffffffu, v, o);
    if (!lane) buf[w] = v;
    __syncthreads();
    if (w == 0) {
        float x = (lane < nw) ? buf[lane] : 0.0f;
#pragma unroll
        for (int o = 8; o; o >>= 1) x += __shfl_xor_sync(0xffffffffu, x, o);
        if (!lane) buf[0] = x;
    }
    __syncthreads();
    float r = buf[0];
    __syncthreads();
    return r;
}

// ---------------- HMMA helpers (sm_80 baseline PTX) ----------------
__device__ __forceinline__ uint32_t smem_u32(const void* p) {
    uint32_t a;
    asm("{ .reg .u64 t; cvta.to.shared.u64 t, %1; cvt.u32.u64 %0, t; }" : "=r"(a) : "l"(p));
    return a;
}
__device__ __forceinline__ void ldsm_x4(uint32_t* r, uint32_t addr) {
    asm volatile("ldmatrix.sync.aligned.m8n8.x4.shared.b16 {%0,%1,%2,%3}, [%4];"
                 : "=r"(r[0]), "=r"(r[1]), "=r"(r[2]), "=r"(r[3]) : "r"(addr));
}
__device__ __forceinline__ void mma_f16(float* d, const uint32_t* a, uint32_t b0, uint32_t b1) {
    asm volatile(
        "mma.sync.aligned.m16n8k16.row.col.f32.f16.f16.f32 "
        "{%0,%1,%2,%3}, {%4,%5,%6,%7}, {%8,%9}, {%0,%1,%2,%3};"
        : "+f"(d[0]), "+f"(d[1]), "+f"(d[2]), "+f"(d[3])
        : "r"(a[0]), "r"(a[1]), "r"(a[2]), "r"(a[3]), "r"(b0), "r"(b1));
}

// grid barrier: arrive = fence + atomicAdd; poll = plain ld.global.cg (no RMW storm)
__device__ __forceinline__ void grid_bar(unsigned target) {
    __syncthreads();
    if (threadIdx.x == 0) {
        __threadfence();
        atomicAdd(&g_cnt, 1u);
        unsigned v;
        do {
            asm volatile("ld.global.cg.u32 %0, [%1];" : "=r"(v) : "l"(&g_cnt));
            if (v >= target) break;
            __nanosleep(32);
        } while (true);
        __threadfence();
    }
    __syncthreads();
}

// ---------------- precompute 1: gram + p ----------------
__global__ void k_pre1(const float* __restrict__ u, const float* __restrict__ v) {
    if (blockIdx.x < 512) {
        __shared__ float ui[RR];
        int i = blockIdx.x;
        if (threadIdx.x < RR) ui[threadIdx.x] = u[i * RR + threadIdx.x];
        __syncthreads();
        int j = threadIdx.x;
        const float* uj = u + j * RR;
        float s = 0.f;
#pragma unroll
        for (int r = 0; r < RR; r++) s += ui[r] * uj[r];
        d_G[i * SS + j] = s;
    } else {
        __shared__ float vk[RR];
        __shared__ float invn;
        int k = blockIdx.x - 512, tid = threadIdx.x;
        if (tid < RR) vk[tid] = v[k * RR + tid];
        __syncthreads();
        if (tid == 0) {
            float s = 0.f;
            for (int r = 0; r < RR; r++) s += vk[r] * vk[r];
            invn = rsqrtf(s);
        }
        __syncthreads();
        const float* ui = u + tid * RR;
        float dot = 0.f;
#pragma unroll
        for (int r = 0; r < RR; r++) dot += ui[r] * vk[r];
        d_p[k * SS + tid] = dot * invn;
    }
}

// ---------------- precompute 2: alpha_a + tau ----------------
__global__ void k_pre2(const float* __restrict__ logp_u, const float* __restrict__ tau) {
    if (blockIdx.x < 16) {
        int row = blockIdx.x * 256 + threadIdx.x;
        const float* r = logp_u + row * AA;
        float m = -3.402823466e38f;
#pragma unroll
        for (int k = 0; k < AA; k++) m = fmaxf(m, r[k]);
        float e[AA], s = 0.f;
#pragma unroll
        for (int k = 0; k < AA; k++) { e[k] = expf(r[k] - m); s += e[k]; }
        float inv = 1.0f / s;
        float* o = d_alpha_a + row * AA;
#pragma unroll
        for (int k = 0; k < AA; k++) o[k] = e[k] * inv;
    } else if (threadIdx.x < HH) {
        int h = threadIdx.x;
        float rate = log1pf(expf(tau[0]));
        float lp = (float)(h + 1) * logf(rate) - rate - lgammaf((float)(h + 2));
        float p = expf(lp);
        float s = p;
#pragma unroll
        for (int o = 16; o; o >>= 1) s += __shfl_xor_sync(0xffffffffu, s, o);
        d_taupdf[h] = p / s;
    }
}

// ---------------- transition softmax ----------------
__global__ void k_trans() {
    __shared__ float buf[16];
    int ki = blockIdx.x;
    int k = ki >> 9, i = ki & 511;
    int j = threadIdx.x;
    float pki = d_p[k * SS + i];
    float w = d_G[i * SS + j] - 2.0f * pki * d_p[k * SS + j];
    float m = bmaxN(w, buf, 16);
    float e = __expf(w - m);
    float s = bsumN(e, buf, 16);
    d_T[(size_t)ki * SS + j] = e / s;
}

// ---------------- transpose + fp16: Tt[j][k*512+i] = T[k][i][j] ----------------
__global__ void k_tpose() {
    __shared__ float tile[64][65];
    int jb = blockIdx.x, it = blockIdx.y, k = blockIdx.z;
    int tid = threadIdx.x;
#pragma unroll
    for (int l = 0; l < 16; l++) {
        int idx = l * 256 + tid;
        int r = idx >> 6, c = idx & 63;
        tile[r][c] = d_T[((size_t)(k * SS + it * 64 + r)) * SS + jb * 64 + c];
    }
    __syncthreads();
#pragma unroll
    for (int l = 0; l < 16; l++) {
        int idx = l * 256 + tid;
        int r = idx >> 6, c = idx & 63;
        d_Tt[(size_t)(jb * 64 + r) * KI + k * SS + it * 64 + c] = __float2half_rn(tile[c][r]);
    }
}

// ---------------- Ã for t=0 + barrier counter reset ----------------
__global__ void k_abel0(const float* __restrict__ b) {
    __shared__ float a_s[AA];
    if (blockIdx.x == 0 && threadIdx.x == 0) g_cnt = 0u;
    int n = blockIdx.x, j = threadIdx.x;
    if (j < AA) a_s[j] = d_alpha_a[n * AA + j];
    __syncthreads();
    float bel = b[n * SS + j];
#pragma unroll
    for (int k = 0; k < AA; k++)
        d_ab[(size_t)n * KI + k * SS + j] = __float2half_rn(a_s[k] * bel);
}

// ---------------- persistent scan: 64 x (HMMA GEMM + bar + post + bar) ----------------
// grid (4 jt, 32 ks) = 128 CTAs (one wave), 512 threads (16 warps), 1 CTA/SM.
// A (Tt fp16, 128j x 256ki) preloaded ONCE into registers (64/lane).
// Warp w: jg = w>>1 -> j rows [16jg,16jg+16), nh = w&1 -> n cols [32nh, 32nh+32).
// Per step: B = ab slice (64n x 256ki) -> smem; 64 HMMA/warp; split-K partials;
// bar; CTAs 0..63 posterior softmax (512 thr, 1 j each) + produce ab(t+1); bar.
#define S_A 0
#define S_B 65536
#define S_PB 98304
#define SCAN_SMEM (98304 + 256)

__global__ __launch_bounds__(512, 1) void k_scan(const float* __restrict__ logp_o,
                                                 float* __restrict__ alpha_b) {
    extern __shared__ __align__(128) char sm[];
    uint32_t sb = smem_u32(sm);
    float* buf = (float*)(sm + S_PB);
    float* a_s = buf + 16;
    int tid = threadIdx.x, w = tid >> 5, lane = tid & 31;
    int jt = blockIdx.x, ks = blockIdx.y;
    int cta = ks * 4 + jt;
    int j0 = jt * 128, ki0 = ks * 256;

    int jg = w >> 1;        // j group (0..7): rows 16jg..16jg+16
    int nh = w & 1;         // n half (0..1): cols 32nh..32nh+32
    int r8 = lane & 7, sub = lane >> 3;
    int arow = 16 * jg + r8 + ((sub & 1) << 3);
    uint32_t a_off = (uint32_t)(arow * 512);
    int acol16 = (sub & 2) << 3;
    uint32_t axor = (uint32_t)(r8 << 4);
    int bcol16 = (sub & 1) << 4;
    int brow_base = ((sub >> 1) << 3) + r8;
    int jl = 16 * jg + (lane >> 2);
    int nb = 2 * (lane & 3);

    // ---- stage A into smem (swizzled), preload fragments into registers ----
    {
        const uint4* gA = (const uint4*)d_Tt;
#pragma unroll
        for (int l = 0; l < 8; l++) {
            int idx = l * 512 + tid;
            int r = idx >> 5, c = idx & 31;
            size_t gi = (size_t)(j0 + r) * (KI / 8) + (ki0 >> 3) + c;
            uint32_t so = (uint32_t)(r * 512 + ((c * 16) ^ ((r & 7) << 4)));
            *(uint4*)(sm + S_A + so) = gA[gi];
        }
    }
    __syncthreads();
    uint32_t areg[16][4];
#pragma unroll
    for (int s = 0; s < 16; s++) {
        uint32_t ac = ((uint32_t)(32 * s + acol16)) ^ axor;
        ldsm_x4(areg[s], sb + S_A + a_off + ac);
    }

    unsigned bar = 0;

    for (int t = 0; t < TT; t++) {
        // ---- B load (written by post on other SMs -> bypass L1 via ldcg) ----
        {
            const uint4* gB = (const uint4*)d_ab;
#pragma unroll
            for (int l = 0; l < 4; l++) {
                int idx = l * 512 + tid;
                int rr = idx >> 5, c = idx & 31;
                uint4 vb = __ldcg(&gB[(size_t)rr * (KI / 8) + (ki0 >> 3) + c]);
                uint32_t so = (uint32_t)(rr * 512 + ((c * 16) ^ ((rr & 7) << 4)));
                *(uint4*)(sm + S_B + so) = vb;
            }
        }
        __syncthreads();

        // ---- fp16 GEMM: warp covers j16 x n32, 16 k-steps, 64 HMMA ----
        float acc[4][4];
#pragma unroll
        for (int tt = 0; tt < 4; tt++)
#pragma unroll
            for (int q = 0; q < 4; q++) acc[tt][q] = 0.f;

#pragma unroll 4
        for (int s = 0; s < 16; s++) {
            uint32_t bh[8];
            uint32_t bc = ((uint32_t)(32 * s + bcol16)) ^ axor;
#pragma unroll
            for (int ql = 0; ql < 2; ql++) {
                int q = 2 * nh + ql;
                uint32_t bo = (uint32_t)((16 * q + brow_base) * 512) + bc;
                ldsm_x4(bh + 4 * ql, sb + S_B + bo);
            }
#pragma unroll
            for (int tt = 0; tt < 4; tt++) {
                int base = 4 * (tt >> 1) + (tt & 1) * 2;
                mma_f16(acc[tt], areg[s], bh[base], bh[base + 1]);
            }
        }
        // ---- epilogue: split-K partials ----
#pragma unroll
        for (int tt = 0; tt < 4; tt++) {
            int n = 32 * nh + 8 * tt + nb;
            float* p0 = &d_partial[((size_t)ks * BB + n) * SS + j0 + jl];
            p0[0] = acc[tt][0];
            p0[SS] = acc[tt][1];
            p0[8] = acc[tt][2];
            p0[SS + 8] = acc[tt][3];
        }
        __syncthreads();  // smem B stable until all warps finish (next fill overwrites)

        grid_bar(++bar * 128u);

        // ---- post: CTAs 0..63, n = cta; thread j = tid ----
        if (cta < 64) {
            int n = cta;
            if (tid < AA && t + 1 < TT)
                a_s[tid] = d_alpha_a[(size_t)(t + 1) * BB * AA + n * AA + tid];
            float s0 = 0.f;
#pragma unroll
            for (int c = 0; c < 32; c++)
                s0 += __ldcg(&d_partial[((size_t)c * BB + n) * SS + tid]);
            const float* lo = logp_o + (size_t)t * BB * SS + (size_t)n * SS;
            float v0 = __logf(s0 + EPSV) + lo[tid];
            float m = bmaxN(v0, buf, 16);
            float e0 = __expf(v0 - m);
            float sum = bsumN(e0, buf, 16);
            float b0 = e0 / sum;
            alpha_b[(size_t)t * BB * SS + (size_t)n * SS + tid] = b0;
            if (t + 1 < TT) {
#pragma unroll
                for (int k = 0; k < AA; k++)
                    d_ab[(size_t)n * KI + k * SS + tid] = __float2half_rn(a_s[k] * b0);
            }
        }
        grid_bar(++bar * 128u);
    }
}

// ---------------- batched plan (outside the sequential chain) ----------------
#define PLAN_SMEM (3 * 64 * 68 * 4)
__global__ __launch_bounds__(256, 4) void k_plan(const float* __restrict__ alpha_b,
                                                 const float* __restrict__ value) {
    extern __shared__ char sm[];
    float(*Vs)[68] = (float(*)[68])sm;
    float(*Bs)[68] = (float(*)[68])(sm + 64 * 68 * 4);
    float(*lg)[68] = (float(*)[68])(sm + 2 * 64 * 68 * 4);

    int n = blockIdx.x, hs = blockIdx.y;
    int h0 = hs * 4;
    int tid = threadIdx.x;
    int tx = tid & 15;
    int ty = tid >> 4;

    unsigned long long acc[4][2];
#pragma unroll
    for (int a = 0; a < 4; a++) { acc[a][0] = 0ull; acc[a][1] = 0ull; }

    for (int c = 0; c < 8; c++) {
        int i0 = c * 64;
#pragma unroll
        for (int l = 0; l < 4; l++) {
            int idx = l * 256 + tid;
            int ii = idx & 63, r4 = idx >> 6;
            float4 vv;
#pragma unroll
            for (int q = 0; q < 4; q++) {
                int row = r4 * 4 + q;
                int hh = row >> 4, kk = row & 15;
                ((float*)&vv)[q] = value[(((size_t)(h0 + hh) * BB + n) * AA + kk) * SS + i0 + ii];
            }
            *(float4*)&Vs[ii][r4 * 4] = vv;
        }
#pragma unroll
        for (int l = 0; l < 4; l++) {
            int idx = l * 256 + tid;
            int ii = idx & 63, t4 = idx >> 6;
            float4 bv;
            bv.x = alpha_b[((size_t)(t4 * 4 + 0) * BB + n) * SS + i0 + ii];
            bv.y = alpha_b[((size_t)(t4 * 4 + 1) * BB + n) * SS + i0 + ii];
            bv.z = alpha_b[((size_t)(t4 * 4 + 2) * BB + n) * SS + i0 + ii];
            bv.w = alpha_b[((size_t)(t4 * 4 + 3) * BB + n) * SS + i0 + ii];
            *(float4*)&Bs[ii][t4 * 4] = bv;
        }
        __syncthreads();
#pragma unroll 8
        for (int ii = 0; ii < 64; ii++) {
            ulonglong2 vv = *(const ulonglong2*)&Vs[ii][tx * 4];
            float4 bv = *(const float4*)&Bs[ii][ty * 4];
            unsigned long long b0 = pack2(bv.x), b1 = pack2(bv.y),
                               b2 = pack2(bv.z), b3 = pack2(bv.w);
            fma2(acc[0][0], b0, vv.x); fma2(acc[0][1], b0, vv.y);
            fma2(acc[1][0], b1, vv.x); fma2(acc[1][1], b1, vv.y);
            fma2(acc[2][0], b2, vv.x); fma2(acc[2][1], b2, vv.y);
            fma2(acc[3][0], b3, vv.x); fma2(acc[3][1], b3, vv.y);
        }
        __syncthreads();
    }
#pragma unroll
    for (int tt = 0; tt < 4; tt++) {
        int t = ty * 4 + tt;
        float2 f0 = *(float2*)&acc[tt][0];
        float2 f1 = *(float2*)&acc[tt][1];
        lg[t][tx * 4] = f0.x;
        lg[t][tx * 4 + 1] = f0.y;
        lg[t][tx * 4 + 2] = f1.x;
        lg[t][tx * 4 + 3] = f1.y;
    }
    __syncthreads();
    {
        int t = tid >> 2, hh = tid & 3;
        const float* row = &lg[t][hh * 16];
        float mm = -3.402823466e38f;
#pragma unroll
        for (int k = 0; k < AA; k++) mm = fmaxf(mm, row[k]);
        float ex[AA], se = 0.f;
#pragma unroll
        for (int k = 0; k < AA; k++) { ex[k] = __expf(row[k] - mm); se += ex[k]; }
        float tw = d_taupdf[h0 + hh] / se;
        float pv[AA];
#pragma unroll
        for (int k = 0; k < AA; k++) pv[k] = ex[k] * tw;
#pragma unroll
        for (int k = 0; k < AA; k++) {
            pv[k] += __shfl_xor_sync(0xffffffffu, pv[k], 1);
            pv[k] += __shfl_xor_sync(0xffffffffu, pv[k], 2);
        }
        float* op = &d_pi_part[(((size_t)hs * TT + t) * BB + n) * AA];
#pragma unroll
        for (int q = 0; q < 4; q++) op[hh * 4 + q] = pv[hh * 4 + q];
    }
}

__global__ void k_pisum(float* __restrict__ api) {
    int idx = blockIdx.x * 256 + threadIdx.x;
    float s = 0.f;
#pragma unroll
    for (int hs = 0; hs < 8; hs++) s += d_pi_part[(size_t)hs * TT * BB * AA + idx];
    api[idx] = s;
}

// ---------------- launch ----------------
extern "C" void kernel_launch(void* const* d_in, const int* in_sizes, int n_in,
                              void* d_out, int out_size) {
    const float* logp_o = (const float*)d_in[0];
    const float* logp_u = (const float*)d_in[1];
    const float* value  = (const float*)d_in[2];
    const float* b      = (const float*)d_in[3];
    const float* u      = (const float*)d_in[4];
    const float* v      = (const float*)d_in[5];
    const float* tau    = (const float*)d_in[6];

    float* out = (float*)d_out;
    float* alpha_b  = out;                         // [T,B,S]
    float* alpha_pi = out + (size_t)TT * BB * SS;  // [T,B,A]

    cudaFuncSetAttribute(k_scan, cudaFuncAttributeMaxDynamicSharedMemorySize, SCAN_SMEM);
    cudaFuncSetAttribute(k_plan, cudaFuncAttributeMaxDynamicSharedMemorySize, PLAN_SMEM);

    k_pre1<<<528, 512>>>(u, v);
    k_pre2<<<17, 256>>>(logp_u, tau);
    k_trans<<<AA * SS, 512>>>();
    {
        dim3 gt(8, 8, 16);
        k_tpose<<<gt, 256>>>();
    }
    k_abel0<<<BB, 512>>>(b);

    {
        dim3 gs(4, 32);
        k_scan<<<gs, 512, SCAN_SMEM>>>(logp_o, alpha_b);
    }

    dim3 gp(BB, 8);
    k_plan<<<gp, 256, PLAN_SMEM>>>(alpha_b, value);
    k_pisum<<<256, 256>>>(alpha_pi);
}